// round 8
// baseline (speedup 1.0000x reference)
#include <cuda_runtime.h>
#include <math.h>

// B=64, C=64, H=W=128, M1=M2=32. BC = 4096 images.
// Reference (einsum labels as written): z = D X D^T ; corners mixed ; out = D z_out D^T.
// Decomposition: out = E X E^T + D Delta D^T,  E = D@D,  Delta corner-supported.

__device__ float g_D [128 * 128];        // DCT-II orthonormal matrix D[k][n]
__device__ float g_ET[128 * 128];        // E^T  (g_ET[a][b] = E[b][a])
__device__ float g_ZcT[2048u * 4096u];   // [kl][bc] corner coeffs / delta (33.5 MB)
__device__ float g_tmpBC[4096u * 2048u]; // [bc][kl] scratch (33.5 MB)
__device__ float g_WT[1024u * 4096u];    // [xy][o*64+i] transposed weights (16.8 MB)

typedef unsigned long long ull;

// Packed fp32x2 helpers (Blackwell): d = a*b + d elementwise on 2 floats.
__device__ __forceinline__ void fma2(ull& d, ull a, ull b) {
    asm("fma.rn.f32x2 %0, %1, %2, %0;" : "+l"(d) : "l"(a), "l"(b));
}
__device__ __forceinline__ ull pack2(float v) {
    ull r; asm("mov.b64 %0, {%1, %1};" : "=l"(r) : "f"(v)); return r;
}

// ---------------------------------------------------------------------------
__global__ void k_initD() {
    int idx = blockIdx.x * 256 + threadIdx.x;          // 16384
    int k = idx >> 7, n = idx & 127;
    double s = (k == 0) ? 0.08838834764831845 : 0.125;
    g_D[idx] = (float)(s * cospi((double)((2 * n + 1) * k) / 256.0));
}

// g_ET[a][b] = E[b][a] = sum_t D[b][t] * D[t][a]
__global__ void k_initE() {
    int a = blockIdx.x, b = threadIdx.x;               // 128 x 128
    double acc = 0.0;
    for (int t = 0; t < 128; t++)
        acc += (double)g_D[b * 128 + t] * (double)g_D[t * 128 + a];
    g_ET[a * 128 + b] = (float)acc;
}

// ---------------------------------------------------------------------------
// Transpose weights: W[(o*64+i)][xy] (4096 x 1024) -> g_WT[xy][o*64+i]
__global__ void k_transW(const float* __restrict__ in) {
    __shared__ float tile[32][33];
    const int c0 = blockIdx.x * 32, r0 = blockIdx.y * 32;
    const int tx = threadIdx.x, ty = threadIdx.y;      // (32, 8)
#pragma unroll
    for (int j = 0; j < 32; j += 8)
        tile[ty + j][tx] = in[(size_t)(r0 + ty + j) * 1024 + c0 + tx];
    __syncthreads();
#pragma unroll
    for (int j = 0; j < 32; j += 8)
        g_WT[(size_t)(c0 + ty + j) * 4096 + r0 + tx] = tile[tx][ty + j];
}

__global__ void k_transT1() {  // g_tmpBC [4096][2048] -> g_ZcT [2048][4096]
    __shared__ float tile[32][33];
    const int c0 = blockIdx.x * 32, r0 = blockIdx.y * 32;
    const int tx = threadIdx.x, ty = threadIdx.y;
#pragma unroll
    for (int j = 0; j < 32; j += 8)
        tile[ty + j][tx] = g_tmpBC[(size_t)(r0 + ty + j) * 2048 + c0 + tx];
    __syncthreads();
#pragma unroll
    for (int j = 0; j < 32; j += 8)
        g_ZcT[(size_t)(c0 + ty + j) * 4096 + r0 + tx] = tile[tx][ty + j];
}

__global__ void k_transT2() {  // g_ZcT [2048][4096] -> g_tmpBC [4096][2048]
    __shared__ float tile[32][33];
    const int c0 = blockIdx.x * 32, r0 = blockIdx.y * 32;
    const int tx = threadIdx.x, ty = threadIdx.y;
#pragma unroll
    for (int j = 0; j < 32; j += 8)
        tile[ty + j][tx] = g_ZcT[(size_t)(r0 + ty + j) * 4096 + c0 + tx];
    __syncthreads();
#pragma unroll
    for (int j = 0; j < 32; j += 8)
        g_tmpBC[(size_t)(c0 + ty + j) * 2048 + r0 + tx] = tile[tx][ty + j];
}

// ---------------------------------------------------------------------------
// Forward corner DCT v2: vectorized smem operands + f32x2.
//   V[m][l]  = sum_n X[m][n] * D[l][n]     (128x32)
//   Zc[ks][l]= sum_m D[k(ks)][m] * V[m][l] (64x32)
// smem words: Ds[64][129]=8256 | DlT[128][36]=4608 | V[128][36]=4608 | xchT[32][132]=4224
// total 21696 words = 86784 B
__global__ void __launch_bounds__(256) k_fwd(const float* __restrict__ x) {
    extern __shared__ float sm[];
    float* Ds   = sm;                           // [64][129]  Ds[ks][m] = D[k(ks)][m]
    float* DlT  = sm + 64 * 129;                // [128][36]  DlT[n][l] = D[l][n], l<32
    float* V    = sm + 64 * 129 + 128 * 36;     // [128][36]
    float* xchT = sm + 64 * 129 + 2 * 128 * 36; // [32][132]  transposed n-chunk; then Zc staging
    const int t  = threadIdx.x;
    const int bc = blockIdx.x;
    const float4* ximg4 = (const float4*)(x + (size_t)bc * 16384);

    for (int i = t; i < 64 * 128; i += 256) {
        int ks = i >> 7, m = i & 127;
        int k = (ks < 32) ? ks : (64 + ks);
        Ds[ks * 129 + m] = g_D[k * 128 + m];
    }
    for (int i = t; i < 128 * 32; i += 256) {
        int n = i >> 5, l = i & 31;
        DlT[n * 36 + l] = g_D[l * 128 + n];
    }

    const int m0 = (t >> 3) * 4;                // 32 m-groups of 4
    const int l0 = (t & 7) * 4;                 // 8 l-groups of 4
    ull acc2[4][2] = {};                        // [m-sub][l-pair]
    for (int nc = 0; nc < 4; nc++) {
        __syncthreads();                        // prev chunk consumed (covers Ds/DlT on nc=0)
        for (int f = t; f < 1024; f += 256) {   // transpose 128m x 32n chunk into xchT[j][m]
            int m = f & 127, jg = f >> 7;       // jg 0..7
            float4 v = ximg4[m * 32 + nc * 8 + jg];
            xchT[(jg * 4 + 0) * 132 + m] = v.x;
            xchT[(jg * 4 + 1) * 132 + m] = v.y;
            xchT[(jg * 4 + 2) * 132 + m] = v.z;
            xchT[(jg * 4 + 3) * 132 + m] = v.w;
        }
        __syncthreads();
#pragma unroll 4
        for (int j = 0; j < 32; j++) {
            const int n = nc * 32 + j;
            float4 xq = *(const float4*)(xchT + j * 132 + m0);   // X[m0..m0+3][n]
            ulonglong2 dv = *(const ulonglong2*)(DlT + n * 36 + l0); // D[l0..l0+3][n] packed
            ull xp[4] = {pack2(xq.x), pack2(xq.y), pack2(xq.z), pack2(xq.w)};
#pragma unroll
            for (int i = 0; i < 4; i++) {
                fma2(acc2[i][0], xp[i], dv.x);
                fma2(acc2[i][1], xp[i], dv.y);
            }
        }
    }
#pragma unroll
    for (int i = 0; i < 4; i++) {
        *(ull*)(V + (m0 + i) * 36 + l0)     = acc2[i][0];
        *(ull*)(V + (m0 + i) * 36 + l0 + 2) = acc2[i][1];
    }
    __syncthreads();

    // stage 2: Zc[ks][l], each thread 2 ks x 4 l
    const int ks0 = (t >> 3) * 2;
    ull a2p[2][2] = {};
#pragma unroll 4
    for (int m = 0; m < 128; m++) {
        ull ap0 = pack2(Ds[ks0 * 129 + m]);
        ull ap1 = pack2(Ds[(ks0 + 1) * 129 + m]);
        ulonglong2 vv = *(const ulonglong2*)(V + m * 36 + l0);
        fma2(a2p[0][0], ap0, vv.x);  fma2(a2p[0][1], ap0, vv.y);
        fma2(a2p[1][0], ap1, vv.x);  fma2(a2p[1][1], ap1, vv.y);
    }
    // stage Zc into xchT (V and xchT are disjoint; linear copy needs a barrier)
#pragma unroll
    for (int i = 0; i < 2; i++) {
        *(ull*)(xchT + (ks0 + i) * 36 + l0)     = a2p[i][0];
        *(ull*)(xchT + (ks0 + i) * 36 + l0 + 2) = a2p[i][1];
    }
    __syncthreads();
    float* outp = g_tmpBC + (size_t)bc * 2048;
    for (int i = t; i < 2048; i += 256) outp[i] = xchT[(i >> 5) * 36 + (i & 31)];
}

// ---------------------------------------------------------------------------
// Channel mixing: delta[b][o] = sum_i z[b][i]*w[o][i] - z[b][o], in place on g_ZcT.
__global__ void __launch_bounds__(256) k_mix() {
    __shared__ float Zs[64 * 65];
    __shared__ float Ws[64 * 65];
    const int kl = blockIdx.x, t = threadIdx.x;
    const int klw = ((kl >> 5) & 31) * 32 + (kl & 31);
    const float4* zin4 = (const float4*)(g_ZcT + (size_t)kl * 4096);
    const float4* win4 = (const float4*)(g_WT + (size_t)klw * 4096);
    for (int i = t; i < 1024; i += 256) {
        int r = i >> 4, c4 = (i & 15) * 4;
        float4 zv = zin4[i];
        float4 wv = win4[i];
        float* zd = Zs + r * 65 + c4;
        float* wd = Ws + r * 65 + c4;
        zd[0] = zv.x; zd[1] = zv.y; zd[2] = zv.z; zd[3] = zv.w;
        wd[0] = wv.x; wd[1] = wv.y; wd[2] = wv.z; wd[3] = wv.w;
    }
    __syncthreads();
    const int b0 = (t >> 4) * 4, o0 = (t & 15) * 4;
    float acc[4][4] = {};
#pragma unroll 4
    for (int i = 0; i < 64; i++) {
        float zb[4], wo[4];
#pragma unroll
        for (int a = 0; a < 4; a++) zb[a] = Zs[(b0 + a) * 65 + i];
#pragma unroll
        for (int c = 0; c < 4; c++) wo[c] = Ws[(o0 + c) * 65 + i];
#pragma unroll
        for (int a = 0; a < 4; a++)
#pragma unroll
            for (int c = 0; c < 4; c++) acc[a][c] = fmaf(zb[a], wo[c], acc[a][c]);
    }
#pragma unroll
    for (int a = 0; a < 4; a++)
#pragma unroll
        for (int c = 0; c < 4; c++) acc[a][c] -= Zs[(b0 + a) * 65 + o0 + c];
    __syncthreads();
#pragma unroll
    for (int a = 0; a < 4; a++)
#pragma unroll
        for (int c = 0; c < 4; c++) Ws[(b0 + a) * 64 + o0 + c] = acc[a][c];
    __syncthreads();
    float* zout = g_ZcT + (size_t)kl * 4096;
    for (int i = t; i < 2048; i += 256)
        ((float2*)zout)[i] = ((float2*)Ws)[i];
}

// ---------------------------------------------------------------------------
// Fused dense path v2 (f32x2), one block per image:
//   T1[m][l]  = sum_n X[m][n] * E[l][n]
//   P[m][l]   = sum_ks D[m][k(ks)] * Delta[ks][l]
//   out[m][n] = sum_j E[m][j]*T1[j][n] + sum_l P[m][l]*D[n][l]
// smem words: Xs 128*132 | Es 128*132 | Dcs 64*132 | dlt 32*132 | dels 64*36 | Ps 128*36
// total 53376 words = 213504 B
__global__ void __launch_bounds__(256) k_main(const float* __restrict__ x,
                                              float* __restrict__ out) {
    extern __shared__ float sm[];
    float* Xs   = sm;                    // [128][132]  X, then T1
    float* Es   = Xs  + 128 * 132;       // [128][132]  row a = g_ET[a][.]
    float* Dcs  = Es  + 128 * 132;       // [64][132]   Dcs[ks][m] = D[m][k(ks)]
    float* dlt  = Dcs + 64 * 132;        // [32][132]   dlt[l][n]  = D[n][l]
    float* dels = dlt + 32 * 132;        // [64][36]    Delta[ks][l]
    float* Ps   = dels + 64 * 36;        // [128][36]
    const int t  = threadIdx.x;
    const int bc = blockIdx.x;

    const float4* ximg4 = (const float4*)(x + (size_t)bc * 16384);
    const float4* et4   = (const float4*)g_ET;
    for (int i4 = t; i4 < 4096; i4 += 256) {
        int r = i4 >> 5, c = i4 & 31;
        *((float4*)(Xs + r * 132) + c) = ximg4[i4];
        *((float4*)(Es + r * 132) + c) = et4[i4];
    }
    for (int i = t; i < 8192; i += 256) {
        int ks = i >> 7, m = i & 127;
        int k = (ks < 32) ? ks : (64 + ks);
        Dcs[ks * 132 + m] = g_D[m * 128 + k];
    }
    for (int i = t; i < 4096; i += 256) {
        int l = i >> 7, n = i & 127;
        dlt[l * 132 + n] = g_D[n * 128 + l];
    }
    {
        const float* din = g_tmpBC + (size_t)bc * 2048;
        for (int i = t; i < 2048; i += 256)
            dels[(i >> 5) * 36 + (i & 31)] = din[i];
    }
    __syncthreads();

    // P stage: 128x32, reduce 64.  4x4 tiles (scalar fp32, small).
    {
        const int m0 = (t >> 3) * 4, l0 = (t & 7) * 4;
        float pa[4][4] = {};
#pragma unroll 4
        for (int ks = 0; ks < 64; ks++) {
            float4 a = *(const float4*)(Dcs + ks * 132 + m0);
            float4 b = *(const float4*)(dels + ks * 36 + l0);
            float av[4] = {a.x, a.y, a.z, a.w};
            float bv[4] = {b.x, b.y, b.z, b.w};
#pragma unroll
            for (int i = 0; i < 4; i++)
#pragma unroll
                for (int c = 0; c < 4; c++) pa[i][c] = fmaf(av[i], bv[c], pa[i][c]);
        }
#pragma unroll
        for (int i = 0; i < 4; i++)
#pragma unroll
            for (int c = 0; c < 4; c++) Ps[(m0 + i) * 36 + l0 + c] = pa[i][c];
    }

    // T1 stage: T1[m][l] = sum_n Xs[m][n] * Es[n][l].  m = tm+16*i, l = tl*8 + {0..7}.
    const int tm = t & 15, tl = t >> 4;
    {
        ull a1p[8][4] = {};
        for (int n = 0; n < 128; n++) {
            ull xp[8];
#pragma unroll
            for (int i = 0; i < 8; i++) xp[i] = pack2(Xs[(tm + 16 * i) * 132 + n]);
            ulonglong2 e01 = *(const ulonglong2*)(Es + n * 132 + tl * 8);
            ulonglong2 e23 = *(const ulonglong2*)(Es + n * 132 + tl * 8 + 4);
#pragma unroll
            for (int i = 0; i < 8; i++) {
                fma2(a1p[i][0], xp[i], e01.x);
                fma2(a1p[i][1], xp[i], e01.y);
                fma2(a1p[i][2], xp[i], e23.x);
                fma2(a1p[i][3], xp[i], e23.y);
            }
        }
        __syncthreads();                   // everyone done reading X; Ps complete
#pragma unroll
        for (int i = 0; i < 8; i++) {      // overwrite Xs with T1 (packed stores)
            float* row = Xs + (tm + 16 * i) * 132 + tl * 8;
            ulonglong2 u0 = {a1p[i][0], a1p[i][1]};
            ulonglong2 u1 = {a1p[i][2], a1p[i][3]};
            *(ulonglong2*)(row)     = u0;
            *(ulonglong2*)(row + 4) = u1;
        }
        __syncthreads();
    }

    // Out stage: out[m][n] = sum_j Es[j][m]*T1[j][n] + sum_l Ps[m][l]*dlt[l][n].
    ull accp[8][4] = {};
    for (int j = 0; j < 128; j++) {
        ull ep[8];
#pragma unroll
        for (int i = 0; i < 8; i++) ep[i] = pack2(Es[j * 132 + tm + 16 * i]);
        ulonglong2 t01 = *(const ulonglong2*)(Xs + j * 132 + tl * 8);
        ulonglong2 t23 = *(const ulonglong2*)(Xs + j * 132 + tl * 8 + 4);
#pragma unroll
        for (int i = 0; i < 8; i++) {
            fma2(accp[i][0], ep[i], t01.x);
            fma2(accp[i][1], ep[i], t01.y);
            fma2(accp[i][2], ep[i], t23.x);
            fma2(accp[i][3], ep[i], t23.y);
        }
    }
    for (int l = 0; l < 32; l++) {
        ull pp[8];
#pragma unroll
        for (int i = 0; i < 8; i++) pp[i] = pack2(Ps[(tm + 16 * i) * 36 + l]);
        ulonglong2 d01 = *(const ulonglong2*)(dlt + l * 132 + tl * 8);
        ulonglong2 d23 = *(const ulonglong2*)(dlt + l * 132 + tl * 8 + 4);
#pragma unroll
        for (int i = 0; i < 8; i++) {
            fma2(accp[i][0], pp[i], d01.x);
            fma2(accp[i][1], pp[i], d01.y);
            fma2(accp[i][2], pp[i], d23.x);
            fma2(accp[i][3], pp[i], d23.y);
        }
    }
    float* op = out + (size_t)bc * 16384;
#pragma unroll
    for (int i = 0; i < 8; i++) {
        int row = tm + 16 * i;
        ulonglong2 u0 = {accp[i][0], accp[i][1]};
        ulonglong2 u1 = {accp[i][2], accp[i][3]};
        *(ulonglong2*)(op + row * 128 + tl * 8)     = u0;
        *(ulonglong2*)(op + row * 128 + tl * 8 + 4) = u1;
    }
}

// ---------------------------------------------------------------------------
extern "C" void kernel_launch(void* const* d_in, const int* in_sizes, int n_in,
                              void* d_out, int out_size) {
    const float* x = (const float*)d_in[0];
    const float* w = (const float*)d_in[1];
    if (n_in >= 2 && in_sizes[0] < in_sizes[1]) {
        const float* tmp = x; x = w; w = tmp;
    }
    float* out = (float*)d_out;

    cudaFuncSetAttribute(k_fwd,  cudaFuncAttributeMaxDynamicSharedMemorySize, 86784);
    cudaFuncSetAttribute(k_main, cudaFuncAttributeMaxDynamicSharedMemorySize, 213504);

    k_initD<<<64, 256>>>();
    k_initE<<<128, 128>>>();
    k_transW<<<dim3(32, 128), dim3(32, 8)>>>(w);
    k_fwd<<<4096, 256, 86784>>>(x);                   // corner z -> g_tmpBC
    k_transT1<<<dim3(64, 128), dim3(32, 8)>>>();      // -> g_ZcT [kl][bc]
    k_mix<<<2048, 256>>>();                           // delta in place
    k_transT2<<<dim3(128, 64), dim3(32, 8)>>>();      // -> g_tmpBC [bc][kl]
    k_main<<<4096, 256, 213504>>>(x, out);            // out = E X E^T + D Delta D^T
}